// round 5
// baseline (speedup 1.0000x reference)
#include <cuda_runtime.h>
#include <cstdint>

#define C      128
#define C4     32
#define GMAX   64
#define LNUM   3
#define NCAP   100000
#define ECAP   1000000
#define NEG    0.01f
#define EPSV   1e-5f
#define SCANB  1024
#define NBMAX  128

typedef unsigned long long ull;

// ---------------- static scratch ----------------
__device__ float g_xw  [(size_t)NCAP * C];   // (x @ W) * dinv[row]
__device__ float g_agg [(size_t)NCAP * C];   // post-aggregation (GCN output + bias)
__device__ int   g_degi[NCAP];
__device__ float g_dinv[NCAP];
__device__ float g_cnt   [GMAX];
__device__ float g_cntinv[GMAX];
__device__ float g_ssum[GMAX * C];
__device__ float g_ssq [GMAX * C];
__device__ float g_A   [GMAX * C];
__device__ float g_B   [GMAX * C];
// CSR by dst
__device__ int g_off [NCAP + 1];
__device__ int g_fill[NCAP];
__device__ int g_esrc[ECAP];
__device__ int g_bsum[NBMAX];

__device__ __forceinline__ ull pack2(float a, float b) {
    ull r; asm("mov.b64 %0, {%1, %2};" : "=l"(r) : "f"(a), "f"(b)); return r;
}
__device__ __forceinline__ float2 unpack(ull p) {
    float2 r; asm("mov.b64 {%0, %1}, %2;" : "=f"(r.x), "=f"(r.y) : "l"(p)); return r;
}
__device__ __forceinline__ void red4(float* p, float4 v) {
    asm volatile("red.global.add.v4.f32 [%0], {%1, %2, %3, %4};"
                 :: "l"(p), "f"(v.x), "f"(v.y), "f"(v.z), "f"(v.w) : "memory");
}

// ---------------- prep ----------------
__global__ void k_zero_prep(int N) {
    int i = blockIdx.x * blockDim.x + threadIdx.x;
    if (i < N)    { g_degi[i] = 0; g_fill[i] = 0; }
    if (i < GMAX) g_cnt[i] = 0.f;
    if (i < GMAX * C) { g_ssum[i] = 0.f; g_ssq[i] = 0.f; }
}

__global__ void k_count(const int* __restrict__ ei, const int* __restrict__ batch,
                        int E, int N) {
    int i = blockIdx.x * blockDim.x + threadIdx.x;
    if (i < E) atomicAdd(&g_degi[ei[E + i]], 1);
    if (i < N) atomicAdd(&g_cnt[batch[i]], 1.0f);
}

__global__ void k_finprep(int N) {
    int i = blockIdx.x * blockDim.x + threadIdx.x;
    if (i < N)    g_dinv[i]   = rsqrtf((float)g_degi[i] + 1.0f);
    if (i < GMAX) g_cntinv[i] = 1.0f / fmaxf(g_cnt[i], 1.0f);
}

// ---------------- prefix scan over degrees -> CSR offsets ----------------
__global__ void k_scan1(int N) {
    __shared__ int red[SCANB];
    int tid = threadIdx.x;
    int i = blockIdx.x * SCANB + tid;
    red[tid] = (i < N) ? g_degi[i] : 0;
    __syncthreads();
#pragma unroll
    for (int s = SCANB / 2; s > 0; s >>= 1) {
        if (tid < s) red[tid] += red[tid + s];
        __syncthreads();
    }
    if (tid == 0) g_bsum[blockIdx.x] = red[0];
}

__global__ void k_scan2(int nb) {
    __shared__ int sb[NBMAX];
    int tid = threadIdx.x;
    int v = (tid < nb) ? g_bsum[tid] : 0;
    sb[tid] = v;
    __syncthreads();
#pragma unroll
    for (int off = 1; off < NBMAX; off <<= 1) {
        int t = (tid >= off) ? sb[tid - off] : 0;
        __syncthreads();
        sb[tid] += t;
        __syncthreads();
    }
    if (tid < nb) g_bsum[tid] = sb[tid] - v;   // exclusive
}

__global__ void k_scan3(int N, int E) {
    __shared__ int s[SCANB];
    int tid = threadIdx.x;
    int i = blockIdx.x * SCANB + tid;
    int v = (i < N) ? g_degi[i] : 0;
    s[tid] = v;
    __syncthreads();
#pragma unroll
    for (int off = 1; off < SCANB; off <<= 1) {
        int t = (tid >= off) ? s[tid - off] : 0;
        __syncthreads();
        s[tid] += t;
        __syncthreads();
    }
    if (i < N) g_off[i] = s[tid] - v + g_bsum[blockIdx.x];
    if (i == 0) g_off[N] = E;
}

__global__ void k_bucket(const int* __restrict__ ei, int E) {
    int i = blockIdx.x * blockDim.x + threadIdx.x;
    if (i >= E) return;
    int src = ei[i], d = ei[E + i];
    int pos = g_off[d] + atomicAdd(&g_fill[d], 1);
    g_esrc[pos] = src;
}

// ---------------- shared GEMM core ----------------
// k-pair packed fma.rn.f32x2. Block 256, tile 64 rows x 128 cols,
// thread: 4 rows x 8 cols. Xp/Wp in smem (96 KB -> 2 CTA/SM).
__device__ __forceinline__ void gemm_core(ull* Xp, ull* Wp, int tid, int row0, int N) {
    __syncthreads();
    int tx = tid & 15, ty = tid >> 4;
    int c0 = tx * 8;
    const ull* xb = Xp + (size_t)(ty * 4) * 64;

    ull acc[4][8];
#pragma unroll
    for (int i = 0; i < 4; i++)
#pragma unroll
        for (int j = 0; j < 8; j++) acc[i][j] = 0ull;

#pragma unroll 4
    for (int kp = 0; kp < 64; kp++) {
        ull xv[4];
#pragma unroll
        for (int i = 0; i < 4; i++) xv[i] = xb[(size_t)i * 64 + kp];
        const ulonglong2* wr = (const ulonglong2*)(Wp + (size_t)kp * 128 + c0);
        ulonglong2 w0 = wr[0], w1 = wr[1], w2 = wr[2], w3 = wr[3];
#pragma unroll
        for (int i = 0; i < 4; i++) {
            asm("fma.rn.f32x2 %0, %1, %2, %0;" : "+l"(acc[i][0]) : "l"(xv[i]), "l"(w0.x));
            asm("fma.rn.f32x2 %0, %1, %2, %0;" : "+l"(acc[i][1]) : "l"(xv[i]), "l"(w0.y));
            asm("fma.rn.f32x2 %0, %1, %2, %0;" : "+l"(acc[i][2]) : "l"(xv[i]), "l"(w1.x));
            asm("fma.rn.f32x2 %0, %1, %2, %0;" : "+l"(acc[i][3]) : "l"(xv[i]), "l"(w1.y));
            asm("fma.rn.f32x2 %0, %1, %2, %0;" : "+l"(acc[i][4]) : "l"(xv[i]), "l"(w2.x));
            asm("fma.rn.f32x2 %0, %1, %2, %0;" : "+l"(acc[i][5]) : "l"(xv[i]), "l"(w2.y));
            asm("fma.rn.f32x2 %0, %1, %2, %0;" : "+l"(acc[i][6]) : "l"(xv[i]), "l"(w3.x));
            asm("fma.rn.f32x2 %0, %1, %2, %0;" : "+l"(acc[i][7]) : "l"(xv[i]), "l"(w3.y));
        }
    }

#pragma unroll
    for (int i = 0; i < 4; i++) {
        int n = row0 + ty * 4 + i;
        if (n >= N) continue;
        float di = g_dinv[n];
        float o[8];
#pragma unroll
        for (int j = 0; j < 8; j++) {
            float2 p = unpack(acc[i][j]);
            o[j] = (p.x + p.y) * di;
        }
        *(float4*)(g_xw + (size_t)n * C + c0)     = make_float4(o[0], o[1], o[2], o[3]);
        *(float4*)(g_xw + (size_t)n * C + c0 + 4) = make_float4(o[4], o[5], o[6], o[7]);
    }
}

__device__ __forceinline__ void load_w(ull* Wp, const float* __restrict__ W, int tid) {
#pragma unroll
    for (int i = 0; i < 32; i++) {
        int idx = tid + 256 * i;
        int kp = idx >> 7, c = idx & 127;
        Wp[idx] = pack2(W[(size_t)(2 * kp) * C + c], W[(size_t)(2 * kp + 1) * C + c]);
    }
}

// layer 0: plain X input
__global__ void __launch_bounds__(256, 2)
k_gemm(const float* __restrict__ X, const float* __restrict__ W, int N) {
    extern __shared__ char smraw[];
    ull* Xp = (ull*)smraw;                       // [64 rows][64 kp]: 32KB
    ull* Wp = (ull*)(smraw + 64 * 64 * 8);       // [64 kp][128 c]:   64KB
    int tid  = threadIdx.x;
    int row0 = blockIdx.x * 64;

    load_w(Wp, W, tid);
    const float4* X4 = (const float4*)X;
#pragma unroll
    for (int i = 0; i < 8; i++) {
        int idx = tid + 256 * i;
        int r = idx >> 5, c4 = idx & 31;
        int n = row0 + r;
        float4 v = (n < N) ? X4[(size_t)n * C4 + c4] : make_float4(0.f, 0.f, 0.f, 0.f);
        ulonglong2 p; p.x = pack2(v.x, v.y); p.y = pack2(v.z, v.w);
        *(ulonglong2*)(Xp + (size_t)r * 64 + c4 * 2) = p;
    }
    gemm_core(Xp, Wp, tid, row0, N);
}

// layers 1,2: input = leaky(agg*A+B); also writes that as previous layer's history
__global__ void __launch_bounds__(256, 2)
k_gemm_norm(const int* __restrict__ batch, const float* __restrict__ W,
            float* __restrict__ hist, int N) {
    extern __shared__ char smraw[];
    ull* Xp = (ull*)smraw;
    ull* Wp = (ull*)(smraw + 64 * 64 * 8);
    int tid  = threadIdx.x;
    int row0 = blockIdx.x * 64;

    load_w(Wp, W, tid);
    const float4* A4 = (const float4*)g_A;
    const float4* B4 = (const float4*)g_B;
    const float4* V4 = (const float4*)g_agg;
#pragma unroll
    for (int i = 0; i < 8; i++) {
        int idx = tid + 256 * i;
        int r = idx >> 5, c4 = idx & 31;
        int n = row0 + r;
        float4 y = make_float4(0.f, 0.f, 0.f, 0.f);
        if (n < N) {
            int g = batch[n];
            float4 v = V4[(size_t)n * C4 + c4];
            float4 a = A4[g * C4 + c4];
            float4 b = B4[g * C4 + c4];
            y.x = fmaf(v.x, a.x, b.x); y.x = fmaxf(y.x, NEG * y.x);
            y.y = fmaf(v.y, a.y, b.y); y.y = fmaxf(y.y, NEG * y.y);
            y.z = fmaf(v.z, a.z, b.z); y.z = fmaxf(y.z, NEG * y.z);
            y.w = fmaf(v.w, a.w, b.w); y.w = fmaxf(y.w, NEG * y.w);
            ((float4*)hist)[(size_t)n * C4 + c4] = y;
        }
        ulonglong2 p; p.x = pack2(y.x, y.y); p.y = pack2(y.z, y.w);
        *(ulonglong2*)(Xp + (size_t)r * 64 + c4 * 2) = p;
    }
    gemm_core(Xp, Wp, tid, row0, N);
}

// ---------------- CSR gather + fused GraphNorm statistics ----------------
// Warp handles 4 consecutive nodes; stats accumulate in registers and flush
// via red.global.v4 on graph change (batch is sorted -> rare).
__global__ void k_gather(const int* __restrict__ batch,
                         const float* __restrict__ bias, int N) {
    int warp = (blockIdx.x * 256 + threadIdx.x) >> 5;
    int lane = threadIdx.x & 31;
    int n0 = warp * 4;
    if (n0 >= N) return;
    const float4* xw4 = (const float4*)g_xw;
    float4 bb = ((const float4*)bias)[lane];

    float4 s = make_float4(0.f, 0.f, 0.f, 0.f), q = s;
    int gcur = batch[n0];

#pragma unroll 1
    for (int m = 0; m < 4; m++) {
        int n = n0 + m;
        if (n >= N) break;
        int g = batch[n];
        if (g != gcur) {
            red4(&g_ssum[gcur * C + lane * 4], s);
            red4(&g_ssq [gcur * C + lane * 4], q);
            s = make_float4(0.f, 0.f, 0.f, 0.f); q = s;
            gcur = g;
        }
        int beg = g_off[n], end = g_off[n + 1];
        float4 a = make_float4(0.f, 0.f, 0.f, 0.f);
        int j = beg;
        for (; j + 8 <= end; j += 8) {
            int i0 = __ldg(&g_esrc[j]),     i1 = __ldg(&g_esrc[j + 1]);
            int i2 = __ldg(&g_esrc[j + 2]), i3 = __ldg(&g_esrc[j + 3]);
            int i4 = __ldg(&g_esrc[j + 4]), i5 = __ldg(&g_esrc[j + 5]);
            int i6 = __ldg(&g_esrc[j + 6]), i7 = __ldg(&g_esrc[j + 7]);
            float4 v0 = xw4[(size_t)i0 * C4 + lane];
            float4 v1 = xw4[(size_t)i1 * C4 + lane];
            float4 v2 = xw4[(size_t)i2 * C4 + lane];
            float4 v3 = xw4[(size_t)i3 * C4 + lane];
            float4 v4 = xw4[(size_t)i4 * C4 + lane];
            float4 v5 = xw4[(size_t)i5 * C4 + lane];
            float4 v6 = xw4[(size_t)i6 * C4 + lane];
            float4 v7 = xw4[(size_t)i7 * C4 + lane];
            a.x += (v0.x + v1.x) + (v2.x + v3.x) + (v4.x + v5.x) + (v6.x + v7.x);
            a.y += (v0.y + v1.y) + (v2.y + v3.y) + (v4.y + v5.y) + (v6.y + v7.y);
            a.z += (v0.z + v1.z) + (v2.z + v3.z) + (v4.z + v5.z) + (v6.z + v7.z);
            a.w += (v0.w + v1.w) + (v2.w + v3.w) + (v4.w + v5.w) + (v6.w + v7.w);
        }
        for (; j + 2 <= end; j += 2) {
            int i0 = __ldg(&g_esrc[j]), i1 = __ldg(&g_esrc[j + 1]);
            float4 v0 = xw4[(size_t)i0 * C4 + lane];
            float4 v1 = xw4[(size_t)i1 * C4 + lane];
            a.x += v0.x + v1.x; a.y += v0.y + v1.y;
            a.z += v0.z + v1.z; a.w += v0.w + v1.w;
        }
        if (j < end) {
            int i0 = __ldg(&g_esrc[j]);
            float4 v0 = xw4[(size_t)i0 * C4 + lane];
            a.x += v0.x; a.y += v0.y; a.z += v0.z; a.w += v0.w;
        }

        float di = g_dinv[n];
        float4 self = xw4[(size_t)n * C4 + lane];
        float4 r;
        r.x = fmaf(a.x + self.x, di, bb.x);
        r.y = fmaf(a.y + self.y, di, bb.y);
        r.z = fmaf(a.z + self.z, di, bb.z);
        r.w = fmaf(a.w + self.w, di, bb.w);
        ((float4*)g_agg)[(size_t)n * C4 + lane] = r;
        s.x += r.x; s.y += r.y; s.z += r.z; s.w += r.w;
        q.x = fmaf(r.x, r.x, q.x); q.y = fmaf(r.y, r.y, q.y);
        q.z = fmaf(r.z, r.z, q.z); q.w = fmaf(r.w, r.w, q.w);
    }
    red4(&g_ssum[gcur * C + lane * 4], s);
    red4(&g_ssq [gcur * C + lane * 4], q);
}

// ---------------- fold stats into affine A,B; zero sums for next layer ----------
__global__ void k_stats(const float* __restrict__ gnw, const float* __restrict__ gnb,
                        const float* __restrict__ gms) {
    int i = blockIdx.x * blockDim.x + threadIdx.x;
    if (i >= GMAX * C) return;
    int g = i >> 7, c = i & (C - 1);
    float ci  = g_cntinv[g];
    float mu  = g_ssum[i] * ci;
    float m2  = g_ssq [i] * ci;
    float sc  = gms[c];
    float var = m2 - mu * mu * (2.f * sc - sc * sc);
    float rstd = rsqrtf(var + EPSV);
    float A = rstd * gnw[c];
    g_A[i] = A;
    g_B[i] = gnb[c] - mu * sc * A;
    g_ssum[i] = 0.f;
    g_ssq [i] = 0.f;
}

// ---------------- final norm + leaky relu (layer L-1 history + output) ----------
__global__ void k_norm(const int* __restrict__ batch, float* __restrict__ hist,
                       float* __restrict__ fin, int N) {
    int t = blockIdx.x * blockDim.x + threadIdx.x;
    int n = t >> 5;
    if (n >= N) return;
    int c4 = t & 31;
    int g = batch[n];
    float4 v = ((const float4*)g_agg)[(size_t)n * C4 + c4];
    float4 a = ((const float4*)g_A)[g * C4 + c4];
    float4 b = ((const float4*)g_B)[g * C4 + c4];
    float4 y;
    y.x = fmaf(v.x, a.x, b.x); y.x = fmaxf(y.x, NEG * y.x);
    y.y = fmaf(v.y, a.y, b.y); y.y = fmaxf(y.y, NEG * y.y);
    y.z = fmaf(v.z, a.z, b.z); y.z = fmaxf(y.z, NEG * y.z);
    y.w = fmaf(v.w, a.w, b.w); y.w = fmaxf(y.w, NEG * y.w);
    ((float4*)hist)[(size_t)n * C4 + c4] = y;
    ((float4*)fin)[(size_t)n * C4 + c4] = y;
}

// ---------------- launch ----------------
extern "C" void kernel_launch(void* const* d_in, const int* in_sizes, int n_in,
                              void* d_out, int out_size) {
    const float* x     = (const float*)d_in[0];
    const int*   ei    = (const int*)d_in[1];
    const int*   batch = (const int*)d_in[2];
    const float* W     = (const float*)d_in[3];
    const float* b     = (const float*)d_in[4];
    const float* gnw   = (const float*)d_in[5];
    const float* gnb   = (const float*)d_in[6];
    const float* gms   = (const float*)d_in[7];
    float* out = (float*)d_out;

    int N = in_sizes[0] / C;
    int E = in_sizes[1] / 2;
    size_t NC = (size_t)N * C;

    const int GEMM_SMEM = 64 * 64 * 8 + 64 * 128 * 8;   // 96 KB
    cudaFuncSetAttribute(k_gemm, cudaFuncAttributeMaxDynamicSharedMemorySize, GEMM_SMEM);
    cudaFuncSetAttribute(k_gemm_norm, cudaFuncAttributeMaxDynamicSharedMemorySize, GEMM_SMEM);

    int zb = (N + 255) / 256;
    int nb = (N + SCANB - 1) / SCANB;
    int gemm_grid = (N + 63) / 64;
    int gath_grid = (N * 8 + 255) / 256;      // warp = 4 nodes

    // harness emits 2 launches first; our index 3 == global index 5 (profiled)
    k_zero_prep<<<zb, 256>>>(N);                                    // 0
    int cm = (E > N ? E : N);
    k_count<<<(cm + 255) / 256, 256>>>(ei, batch, E, N);            // 1
    k_finprep<<<zb, 256>>>(N);                                      // 2
    k_gemm<<<gemm_grid, 256, GEMM_SMEM>>>(x, W, N);                 // 3 <- profiled
    k_scan1<<<nb, SCANB>>>(N);
    k_scan2<<<1, NBMAX>>>(nb);
    k_scan3<<<nb, SCANB>>>(N, E);
    k_bucket<<<(E + 255) / 256, 256>>>(ei, E);

    for (int l = 0; l < LNUM; l++) {
        if (l > 0)
            k_gemm_norm<<<gemm_grid, 256, GEMM_SMEM>>>(batch, W + (size_t)l * C * C,
                                                       out + NC * (size_t)l, N);
        k_gather<<<gath_grid, 256>>>(batch, b + (size_t)l * C, N);
        k_stats<<<(GMAX * C + 255) / 256, 256>>>(gnw + (size_t)l * C,
                                                 gnb + (size_t)l * C,
                                                 gms + (size_t)l * C);
    }
    k_norm<<<((size_t)N * 32 + 255) / 256, 256>>>(batch, out + NC * (size_t)LNUM, out, N);
}

// round 7
// speedup vs baseline: 2.3799x; 2.3799x over previous
#include <cuda_runtime.h>
#include <cstdint>

#define C      128
#define C4     32
#define GMAX   64
#define LNUM   3
#define NCAP   100000
#define ECAP   1000000
#define NEG    0.01f
#define EPSV   1e-5f
#define SCANB  1024
#define NBMAX  128

typedef unsigned long long ull;

// ---------------- static scratch ----------------
__device__ float g_xw  [(size_t)NCAP * C];   // (x @ W) * dinv[row]
__device__ float g_agg [(size_t)NCAP * C];   // post-aggregation (GCN output + bias)
__device__ int   g_degi[NCAP];
__device__ float g_dinv[NCAP];
__device__ float g_cnt   [GMAX];
__device__ float g_cntinv[GMAX];
__device__ float g_ssum[GMAX * C];
__device__ float g_ssq [GMAX * C];
__device__ float g_A   [GMAX * C];
__device__ float g_B   [GMAX * C];
// CSR by dst
__device__ int g_off [NCAP + 1];
__device__ int g_fill[NCAP];
__device__ int g_esrc[ECAP];
__device__ int g_bsum[NBMAX];

__device__ __forceinline__ ull pack2(float a, float b) {
    ull r; asm("mov.b64 %0, {%1, %2};" : "=l"(r) : "f"(a), "f"(b)); return r;
}
__device__ __forceinline__ float2 unpack(ull p) {
    float2 r; asm("mov.b64 {%0, %1}, %2;" : "=f"(r.x), "=f"(r.y) : "l"(p)); return r;
}
__device__ __forceinline__ void red4(float* p, float4 v) {
    asm volatile("red.global.add.v4.f32 [%0], {%1, %2, %3, %4};"
                 :: "l"(p), "f"(v.x), "f"(v.y), "f"(v.z), "f"(v.w) : "memory");
}

// ---------------- prep ----------------
__global__ void k_zero_prep(int N) {
    int i = blockIdx.x * blockDim.x + threadIdx.x;
    if (i < N)    { g_degi[i] = 0; g_fill[i] = 0; }
    if (i < GMAX) g_cnt[i] = 0.f;
    if (i < GMAX * C) { g_ssum[i] = 0.f; g_ssq[i] = 0.f; }
}

__global__ void k_count(const int* __restrict__ ei, const int* __restrict__ batch,
                        int E, int N) {
    int i = blockIdx.x * blockDim.x + threadIdx.x;
    if (i < E) atomicAdd(&g_degi[ei[E + i]], 1);
    if (i < N) atomicAdd(&g_cnt[batch[i]], 1.0f);
}

__global__ void k_finprep(int N) {
    int i = blockIdx.x * blockDim.x + threadIdx.x;
    if (i < N)    g_dinv[i]   = rsqrtf((float)g_degi[i] + 1.0f);
    if (i < GMAX) g_cntinv[i] = 1.0f / fmaxf(g_cnt[i], 1.0f);
}

// ---------------- prefix scan over degrees -> CSR offsets ----------------
__global__ void k_scan1(int N) {
    __shared__ int red[SCANB];
    int tid = threadIdx.x;
    int i = blockIdx.x * SCANB + tid;
    red[tid] = (i < N) ? g_degi[i] : 0;
    __syncthreads();
#pragma unroll
    for (int s = SCANB / 2; s > 0; s >>= 1) {
        if (tid < s) red[tid] += red[tid + s];
        __syncthreads();
    }
    if (tid == 0) g_bsum[blockIdx.x] = red[0];
}

__global__ void k_scan2(int nb) {
    __shared__ int sb[NBMAX];
    int tid = threadIdx.x;
    int v = (tid < nb) ? g_bsum[tid] : 0;
    sb[tid] = v;
    __syncthreads();
#pragma unroll
    for (int off = 1; off < NBMAX; off <<= 1) {
        int t = (tid >= off) ? sb[tid - off] : 0;
        __syncthreads();
        sb[tid] += t;
        __syncthreads();
    }
    if (tid < nb) g_bsum[tid] = sb[tid] - v;   // exclusive
}

__global__ void k_scan3(int N, int E) {
    __shared__ int s[SCANB];
    int tid = threadIdx.x;
    int i = blockIdx.x * SCANB + tid;
    int v = (i < N) ? g_degi[i] : 0;
    s[tid] = v;
    __syncthreads();
#pragma unroll
    for (int off = 1; off < SCANB; off <<= 1) {
        int t = (tid >= off) ? s[tid - off] : 0;
        __syncthreads();
        s[tid] += t;
        __syncthreads();
    }
    if (i < N) g_off[i] = s[tid] - v + g_bsum[blockIdx.x];
    if (i == 0) g_off[N] = E;
}

__global__ void k_bucket(const int* __restrict__ ei, int E) {
    int i = blockIdx.x * blockDim.x + threadIdx.x;
    if (i >= E) return;
    int src = ei[i], d = ei[E + i];
    int pos = g_off[d] + atomicAdd(&g_fill[d], 1);
    g_esrc[pos] = src;
}

// ---------------- shared GEMM core (conflict-free interleaved columns) ------
// Thread (tx=tid&15, ty=tid>>4): 4 rows x 8 cols.
// Columns: {2*tx + 32*j, 2*tx + 32*j + 1 : j=0..3}.
// W ulonglong2 load for pair j sits at byte offset 16*tx + 256*j within the
// kp row -> each 8-thread LDS.128 phase covers banks 0..31 exactly once.
__device__ __forceinline__ void gemm_core(ull* Xp, ull* Wp, int tid, int row0, int N) {
    __syncthreads();
    int tx = tid & 15, ty = tid >> 4;
    const ull* xb = Xp + (size_t)(ty * 4) * 64;
    const ulonglong2* wb = (const ulonglong2*)(Wp + 2 * tx);

    ull acc[4][8];
#pragma unroll
    for (int i = 0; i < 4; i++)
#pragma unroll
        for (int j = 0; j < 8; j++) acc[i][j] = 0ull;

#pragma unroll 4
    for (int kp = 0; kp < 64; kp++) {
        ull xv[4];
#pragma unroll
        for (int i = 0; i < 4; i++) xv[i] = xb[(size_t)i * 64 + kp];
        const ulonglong2* wr = wb + (size_t)kp * 64;   // 128 ull / 2 per row
        ulonglong2 w0 = wr[0];        // cols 2tx,   2tx+1
        ulonglong2 w1 = wr[16];       // cols 2tx+32, +33
        ulonglong2 w2 = wr[32];       // cols 2tx+64, +65
        ulonglong2 w3 = wr[48];       // cols 2tx+96, +97
#pragma unroll
        for (int i = 0; i < 4; i++) {
            asm("fma.rn.f32x2 %0, %1, %2, %0;" : "+l"(acc[i][0]) : "l"(xv[i]), "l"(w0.x));
            asm("fma.rn.f32x2 %0, %1, %2, %0;" : "+l"(acc[i][1]) : "l"(xv[i]), "l"(w0.y));
            asm("fma.rn.f32x2 %0, %1, %2, %0;" : "+l"(acc[i][2]) : "l"(xv[i]), "l"(w1.x));
            asm("fma.rn.f32x2 %0, %1, %2, %0;" : "+l"(acc[i][3]) : "l"(xv[i]), "l"(w1.y));
            asm("fma.rn.f32x2 %0, %1, %2, %0;" : "+l"(acc[i][4]) : "l"(xv[i]), "l"(w2.x));
            asm("fma.rn.f32x2 %0, %1, %2, %0;" : "+l"(acc[i][5]) : "l"(xv[i]), "l"(w2.y));
            asm("fma.rn.f32x2 %0, %1, %2, %0;" : "+l"(acc[i][6]) : "l"(xv[i]), "l"(w3.x));
            asm("fma.rn.f32x2 %0, %1, %2, %0;" : "+l"(acc[i][7]) : "l"(xv[i]), "l"(w3.y));
        }
    }

#pragma unroll
    for (int i = 0; i < 4; i++) {
        int n = row0 + ty * 4 + i;
        if (n >= N) continue;
        float di = g_dinv[n];
        float* dst = g_xw + (size_t)n * C + 2 * tx;
#pragma unroll
        for (int j = 0; j < 4; j++) {
            float2 pa = unpack(acc[i][2 * j]);
            float2 pb = unpack(acc[i][2 * j + 1]);
            *(float2*)(dst + 32 * j) = make_float2((pa.x + pa.y) * di,
                                                   (pb.x + pb.y) * di);
        }
    }
}

__device__ __forceinline__ void load_w(ull* Wp, const float* __restrict__ W, int tid) {
#pragma unroll
    for (int i = 0; i < 32; i++) {
        int idx = tid + 256 * i;
        int kp = idx >> 7, c = idx & 127;
        Wp[idx] = pack2(W[(size_t)(2 * kp) * C + c], W[(size_t)(2 * kp + 1) * C + c]);
    }
}

// layer 0: plain X input
__global__ void __launch_bounds__(256, 2)
k_gemm(const float* __restrict__ X, const float* __restrict__ W, int N) {
    extern __shared__ char smraw[];
    ull* Xp = (ull*)smraw;                       // [64 rows][64 kp]: 32KB
    ull* Wp = (ull*)(smraw + 64 * 64 * 8);       // [64 kp][128 c]:   64KB
    int tid  = threadIdx.x;
    int row0 = blockIdx.x * 64;

    load_w(Wp, W, tid);
    const float4* X4 = (const float4*)X;
#pragma unroll
    for (int i = 0; i < 8; i++) {
        int idx = tid + 256 * i;
        int r = idx >> 5, c4 = idx & 31;
        int n = row0 + r;
        float4 v = (n < N) ? X4[(size_t)n * C4 + c4] : make_float4(0.f, 0.f, 0.f, 0.f);
        ulonglong2 p; p.x = pack2(v.x, v.y); p.y = pack2(v.z, v.w);
        *(ulonglong2*)(Xp + (size_t)r * 64 + c4 * 2) = p;
    }
    gemm_core(Xp, Wp, tid, row0, N);
}

// layers 1,2: input = leaky(agg*A+B); also writes that as previous layer's history
__global__ void __launch_bounds__(256, 2)
k_gemm_norm(const int* __restrict__ batch, const float* __restrict__ W,
            float* __restrict__ hist, int N) {
    extern __shared__ char smraw[];
    ull* Xp = (ull*)smraw;
    ull* Wp = (ull*)(smraw + 64 * 64 * 8);
    int tid  = threadIdx.x;
    int row0 = blockIdx.x * 64;

    load_w(Wp, W, tid);
    const float4* A4 = (const float4*)g_A;
    const float4* B4 = (const float4*)g_B;
    const float4* V4 = (const float4*)g_agg;
#pragma unroll
    for (int i = 0; i < 8; i++) {
        int idx = tid + 256 * i;
        int r = idx >> 5, c4 = idx & 31;
        int n = row0 + r;
        float4 y = make_float4(0.f, 0.f, 0.f, 0.f);
        if (n < N) {
            int g = batch[n];
            float4 v = V4[(size_t)n * C4 + c4];
            float4 a = A4[g * C4 + c4];
            float4 b = B4[g * C4 + c4];
            y.x = fmaf(v.x, a.x, b.x); y.x = fmaxf(y.x, NEG * y.x);
            y.y = fmaf(v.y, a.y, b.y); y.y = fmaxf(y.y, NEG * y.y);
            y.z = fmaf(v.z, a.z, b.z); y.z = fmaxf(y.z, NEG * y.z);
            y.w = fmaf(v.w, a.w, b.w); y.w = fmaxf(y.w, NEG * y.w);
            ((float4*)hist)[(size_t)n * C4 + c4] = y;
        }
        ulonglong2 p; p.x = pack2(y.x, y.y); p.y = pack2(y.z, y.w);
        *(ulonglong2*)(Xp + (size_t)r * 64 + c4 * 2) = p;
    }
    gemm_core(Xp, Wp, tid, row0, N);
}

// ---------------- CSR gather + fused GraphNorm statistics ----------------
__global__ void k_gather(const int* __restrict__ batch,
                         const float* __restrict__ bias, int N) {
    int warp = (blockIdx.x * 256 + threadIdx.x) >> 5;
    int lane = threadIdx.x & 31;
    int n0 = warp * 4;
    if (n0 >= N) return;
    const float4* xw4 = (const float4*)g_xw;
    float4 bb = ((const float4*)bias)[lane];

    float4 s = make_float4(0.f, 0.f, 0.f, 0.f), q = s;
    int gcur = batch[n0];

#pragma unroll 1
    for (int m = 0; m < 4; m++) {
        int n = n0 + m;
        if (n >= N) break;
        int g = batch[n];
        if (g != gcur) {
            red4(&g_ssum[gcur * C + lane * 4], s);
            red4(&g_ssq [gcur * C + lane * 4], q);
            s = make_float4(0.f, 0.f, 0.f, 0.f); q = s;
            gcur = g;
        }
        int beg = g_off[n], end = g_off[n + 1];
        float4 a = make_float4(0.f, 0.f, 0.f, 0.f);
        int j = beg;
        for (; j + 8 <= end; j += 8) {
            int i0 = __ldg(&g_esrc[j]),     i1 = __ldg(&g_esrc[j + 1]);
            int i2 = __ldg(&g_esrc[j + 2]), i3 = __ldg(&g_esrc[j + 3]);
            int i4 = __ldg(&g_esrc[j + 4]), i5 = __ldg(&g_esrc[j + 5]);
            int i6 = __ldg(&g_esrc[j + 6]), i7 = __ldg(&g_esrc[j + 7]);
            float4 v0 = xw4[(size_t)i0 * C4 + lane];
            float4 v1 = xw4[(size_t)i1 * C4 + lane];
            float4 v2 = xw4[(size_t)i2 * C4 + lane];
            float4 v3 = xw4[(size_t)i3 * C4 + lane];
            float4 v4 = xw4[(size_t)i4 * C4 + lane];
            float4 v5 = xw4[(size_t)i5 * C4 + lane];
            float4 v6 = xw4[(size_t)i6 * C4 + lane];
            float4 v7 = xw4[(size_t)i7 * C4 + lane];
            a.x += (v0.x + v1.x) + (v2.x + v3.x) + (v4.x + v5.x) + (v6.x + v7.x);
            a.y += (v0.y + v1.y) + (v2.y + v3.y) + (v4.y + v5.y) + (v6.y + v7.y);
            a.z += (v0.z + v1.z) + (v2.z + v3.z) + (v4.z + v5.z) + (v6.z + v7.z);
            a.w += (v0.w + v1.w) + (v2.w + v3.w) + (v4.w + v5.w) + (v6.w + v7.w);
        }
        for (; j + 2 <= end; j += 2) {
            int i0 = __ldg(&g_esrc[j]), i1 = __ldg(&g_esrc[j + 1]);
            float4 v0 = xw4[(size_t)i0 * C4 + lane];
            float4 v1 = xw4[(size_t)i1 * C4 + lane];
            a.x += v0.x + v1.x; a.y += v0.y + v1.y;
            a.z += v0.z + v1.z; a.w += v0.w + v1.w;
        }
        if (j < end) {
            int i0 = __ldg(&g_esrc[j]);
            float4 v0 = xw4[(size_t)i0 * C4 + lane];
            a.x += v0.x; a.y += v0.y; a.z += v0.z; a.w += v0.w;
        }

        float di = g_dinv[n];
        float4 self = xw4[(size_t)n * C4 + lane];
        float4 r;
        r.x = fmaf(a.x + self.x, di, bb.x);
        r.y = fmaf(a.y + self.y, di, bb.y);
        r.z = fmaf(a.z + self.z, di, bb.z);
        r.w = fmaf(a.w + self.w, di, bb.w);
        ((float4*)g_agg)[(size_t)n * C4 + lane] = r;
        s.x += r.x; s.y += r.y; s.z += r.z; s.w += r.w;
        q.x = fmaf(r.x, r.x, q.x); q.y = fmaf(r.y, r.y, q.y);
        q.z = fmaf(r.z, r.z, q.z); q.w = fmaf(r.w, r.w, q.w);
    }
    red4(&g_ssum[gcur * C + lane * 4], s);
    red4(&g_ssq [gcur * C + lane * 4], q);
}

// ---------------- fold stats into affine A,B; zero sums for next layer ----------
__global__ void k_stats(const float* __restrict__ gnw, const float* __restrict__ gnb,
                        const float* __restrict__ gms) {
    int i = blockIdx.x * blockDim.x + threadIdx.x;
    if (i >= GMAX * C) return;
    int g = i >> 7, c = i & (C - 1);
    float ci  = g_cntinv[g];
    float mu  = g_ssum[i] * ci;
    float m2  = g_ssq [i] * ci;
    float sc  = gms[c];
    float var = m2 - mu * mu * (2.f * sc - sc * sc);
    float rstd = rsqrtf(var + EPSV);
    float A = rstd * gnw[c];
    g_A[i] = A;
    g_B[i] = gnb[c] - mu * sc * A;
    g_ssum[i] = 0.f;
    g_ssq [i] = 0.f;
}

// ---------------- final norm + leaky relu (layer L-1 history + output) ----------
__global__ void k_norm(const int* __restrict__ batch, float* __restrict__ hist,
                       float* __restrict__ fin, int N) {
    int t = blockIdx.x * blockDim.x + threadIdx.x;
    int n = t >> 5;
    if (n >= N) return;
    int c4 = t & 31;
    int g = batch[n];
    float4 v = ((const float4*)g_agg)[(size_t)n * C4 + c4];
    float4 a = ((const float4*)g_A)[g * C4 + c4];
    float4 b = ((const float4*)g_B)[g * C4 + c4];
    float4 y;
    y.x = fmaf(v.x, a.x, b.x); y.x = fmaxf(y.x, NEG * y.x);
    y.y = fmaf(v.y, a.y, b.y); y.y = fmaxf(y.y, NEG * y.y);
    y.z = fmaf(v.z, a.z, b.z); y.z = fmaxf(y.z, NEG * y.z);
    y.w = fmaf(v.w, a.w, b.w); y.w = fmaxf(y.w, NEG * y.w);
    ((float4*)hist)[(size_t)n * C4 + c4] = y;
    ((float4*)fin)[(size_t)n * C4 + c4] = y;
}

// ---------------- launch ----------------
extern "C" void kernel_launch(void* const* d_in, const int* in_sizes, int n_in,
                              void* d_out, int out_size) {
    const float* x     = (const float*)d_in[0];
    const int*   ei    = (const int*)d_in[1];
    const int*   batch = (const int*)d_in[2];
    const float* W     = (const float*)d_in[3];
    const float* b     = (const float*)d_in[4];
    const float* gnw   = (const float*)d_in[5];
    const float* gnb   = (const float*)d_in[6];
    const float* gms   = (const float*)d_in[7];
    float* out = (float*)d_out;

    int N = in_sizes[0] / C;
    int E = in_sizes[1] / 2;
    size_t NC = (size_t)N * C;

    const int GEMM_SMEM = 64 * 64 * 8 + 64 * 128 * 8;   // 96 KB
    cudaFuncSetAttribute(k_gemm, cudaFuncAttributeMaxDynamicSharedMemorySize, GEMM_SMEM);
    cudaFuncSetAttribute(k_gemm_norm, cudaFuncAttributeMaxDynamicSharedMemorySize, GEMM_SMEM);

    int zb = (N + 255) / 256;
    int nb = (N + SCANB - 1) / SCANB;
    int gemm_grid = (N + 63) / 64;
    int gath_grid = (N * 8 + 255) / 256;      // warp = 4 nodes

    // harness emits 2 launches first; our index 3 == global index 5 (profiled)
    k_zero_prep<<<zb, 256>>>(N);                                    // 0
    int cm = (E > N ? E : N);
    k_count<<<(cm + 255) / 256, 256>>>(ei, batch, E, N);            // 1
    k_finprep<<<zb, 256>>>(N);                                      // 2
    k_gemm<<<gemm_grid, 256, GEMM_SMEM>>>(x, W, N);                 // 3 <- profiled
    k_scan1<<<nb, SCANB>>>(N);
    k_scan2<<<1, NBMAX>>>(nb);
    k_scan3<<<nb, SCANB>>>(N, E);
    k_bucket<<<(E + 255) / 256, 256>>>(ei, E);

    for (int l = 0; l < LNUM; l++) {
        if (l > 0)
            k_gemm_norm<<<gemm_grid, 256, GEMM_SMEM>>>(batch, W + (size_t)l * C * C,
                                                       out + NC * (size_t)l, N);
        k_gather<<<gath_grid, 256>>>(batch, b + (size_t)l * C, N);
        k_stats<<<(GMAX * C + 255) / 256, 256>>>(gnw + (size_t)l * C,
                                                 gnb + (size_t)l * C,
                                                 gms + (size_t)l * C);
    }
    k_norm<<<((size_t)N * 32 + 255) / 256, 256>>>(batch, out + NC * (size_t)LNUM, out, N);
}